// round 3
// baseline (speedup 1.0000x reference)
#include <cuda_runtime.h>

#define CB 4
#define CC 96
#define CHh 128
#define CWw 128
#define CL (CHh*CWw)      // 16384
#define CK 2
#define CN 1              // !!! N = 1 (was wrongly 6)
#define CR 6
#define CD (CR + 2*CN)    // 8 rows of x_proj output
#define CO (2*CC)         // 192

// ---------------- device scratch (allocation-free) ----------------
__device__ float  g_xc[CB*CC*CL];        // conv input (pre-activation x branch)
__device__ float  g_z [CB*CC*CL];        // silu(z) gate
__device__ float  g_u [CB*CC*CL];        // post conv+silu
__device__ float2 g_dd[CB*CK*CC*CL];     // {delta, delta*u} per (b,k,c,p)
__device__ float2 g_bc[CB*CK*CL];        // {B, C} per (b,k,p)   (N=1)
__device__ float  g_y0[CB*CC*CL];        // k=0 scan output (physical order)
__device__ float  g_y1[CB*CC*CL];        // k=1 scan output (physical order)
__device__ float  g_wt1[CC*CO];          // transposed in_proj  [c][o]
__device__ float  g_wt2[CC*CC];          // transposed out_proj [c][o]

__device__ __forceinline__ float ex2f(float x){
    float y; asm("ex2.approx.f32 %0, %1;" : "=f"(y) : "f"(x)); return y;
}
__device__ __forceinline__ float sigmoidf_(float x){
    return 1.f / (1.f + __expf(-x));
}

// ---------------- K0: transpose weights ----------------
__global__ void k_transpose(const float* __restrict__ w1, const float* __restrict__ w2){
    int t = blockIdx.x*256 + threadIdx.x;
    if (t < CO*CC){ int o = t / CC, c = t % CC; g_wt1[c*CO + o] = w1[t]; }
    if (t < CC*CC){ int o = t / CC, c = t % CC; g_wt2[c*CC + o] = w2[t]; }
}

// ---------------- K1: in_proj GEMM 192x96 over (b,l) tiles of 64 ----------------
// 256 threads = 16(to) x 16(tl); thread computes o in [to*12, to*12+12), l in [tl*4, tl*4+4)
__global__ void k_inproj(const float* __restrict__ x){
    __shared__ float xsm[CC][68];
    int b  = blockIdx.y;
    int l0 = blockIdx.x * 64;
    int t  = threadIdx.x;

    for (int i = t; i < CC*64; i += 256){
        int c = i >> 6, l = i & 63;
        xsm[c][l] = x[(b*CC + c)*CL + l0 + l];
    }
    __syncthreads();

    int to = t & 15, tl = t >> 4;
    int o0 = to * 12;
    int lb = tl * 4;

    float acc[12][4];
    #pragma unroll
    for (int j = 0; j < 12; j++)
        #pragma unroll
        for (int i = 0; i < 4; i++) acc[j][i] = 0.f;

    #pragma unroll 4
    for (int c = 0; c < CC; c++){
        float4 xv = *(const float4*)&xsm[c][lb];
        const float4* wp = (const float4*)&g_wt1[c*CO + o0];
        float4 w0 = wp[0], w1 = wp[1], w2 = wp[2];
        float wv[12] = {w0.x,w0.y,w0.z,w0.w, w1.x,w1.y,w1.z,w1.w, w2.x,w2.y,w2.z,w2.w};
        float xr[4]  = {xv.x,xv.y,xv.z,xv.w};
        #pragma unroll
        for (int j = 0; j < 12; j++)
            #pragma unroll
            for (int i = 0; i < 4; i++)
                acc[j][i] = fmaf(wv[j], xr[i], acc[j][i]);
    }
    __syncthreads();   // done reading xsm; reuse for output staging

    // stage and write in two halves: half 0 -> xc (o<96), half 1 -> z (silu)
    for (int half = 0; half < 2; half++){
        if ((to < 8) == (half == 0)){
            int ob = o0 - half*96;
            #pragma unroll
            for (int j = 0; j < 12; j++)
                #pragma unroll
                for (int i = 0; i < 4; i++)
                    xsm[ob + j][lb + i] = acc[j][i];
        }
        __syncthreads();
        for (int i = t; i < CC*64; i += 256){
            int row = i >> 6, l = i & 63;
            float v = xsm[row][l];
            int idx = (b*CC + row)*CL + l0 + l;
            if (half == 0) g_xc[idx] = v;
            else           g_z[idx]  = v * sigmoidf_(v);   // store silu(z)
        }
        __syncthreads();
    }
}

// ---------------- K2: depthwise 3x3 conv + bias + SiLU ----------------
__global__ void k_conv(const float* __restrict__ cw, const float* __restrict__ cb){
    int idx = blockIdx.x*256 + threadIdx.x;
    if (idx >= CB*CC*CL) return;
    int w  = idx & (CWw-1);
    int h  = (idx >> 7) & (CHh-1);
    int bc = idx >> 14;
    int c  = bc % CC;
    const float* src = g_xc + bc*CL;
    float wl[9];
    #pragma unroll
    for (int j = 0; j < 9; j++) wl[j] = __ldg(&cw[c*9 + j]);
    float acc = __ldg(&cb[c]);
    #pragma unroll
    for (int dh = -1; dh <= 1; dh++){
        int hh = h + dh;
        if (hh < 0 || hh >= CHh) continue;
        #pragma unroll
        for (int dw = -1; dw <= 1; dw++){
            int ww = w + dw;
            if (ww < 0 || ww >= CWw) continue;
            acc = fmaf(wl[(dh+1)*3 + (dw+1)], src[hh*CWw + ww], acc);
        }
    }
    g_u[idx] = acc * sigmoidf_(acc);
}

// ---------------- K3: x_proj (C->8), B/C extraction, delta = softplus(dt_proj) ----------------
__global__ void k_xproj(const float* __restrict__ xw, const float* __restrict__ dtw,
                        const float* __restrict__ dtb){
    __shared__ float usm[CC][68];
    __shared__ float dsm[CK*CD][68];
    int b  = blockIdx.y;
    int p0 = blockIdx.x * 64;
    int t  = threadIdx.x;

    for (int i = t; i < CC*64; i += 256){
        int c = i >> 6, pp = i & 63;
        usm[c][pp] = g_u[(b*CC + c)*CL + p0 + pp];
    }
    __syncthreads();

    // projections: CK*CD = 16 rows (k*CD+d) x 64 positions
    for (int task = t; task < CK*CD*64; task += 256){
        int kd = task >> 6, pp = task & 63;
        const float* wrow = xw + kd*CC;
        float s = 0.f;
        #pragma unroll 8
        for (int c = 0; c < CC; c++) s = fmaf(__ldg(&wrow[c]), usm[c][pp], s);
        dsm[kd][pp] = s;
        int k = kd / CD, d = kd % CD;
        if (d >= CR){
            // d == CR -> B, d == CR+1 -> C
            float* bcf = (float*)&g_bc[(b*CK + k)*CL + p0 + pp];
            bcf[d - CR] = s;
        }
    }
    __syncthreads();

    // delta: softplus(dt_proj(dts) + b), store {delta, delta*u}
    for (int task = t; task < CK*CC*64; task += 256){
        int kc = task >> 6, pp = task & 63;
        int k = kc / CC, c = kc % CC;
        const float* dwr = dtw + (k*CC + c)*CR;
        float s = __ldg(&dtb[k*CC + c]);
        #pragma unroll
        for (int r = 0; r < CR; r++) s = fmaf(__ldg(&dwr[r]), dsm[k*CD + r][pp], s);
        float delta = (s > 20.f) ? s : log1pf(__expf(s));
        float uv = usm[c][pp];
        g_dd[((b*CK + k)*CC + c)*CL + p0 + pp] = make_float2(delta, delta*uv);
    }
}

// ---------------- K4: selective scan (N=1), warp per (b,k,c), chunked w/ warp shuffle ----------------
__global__ void k_scan(const float* __restrict__ Alogs, const float* __restrict__ Ds){
    int gw   = (blockIdx.x*blockDim.x + threadIdx.x) >> 5;   // 0..767
    int lane = threadIdx.x & 31;
    int b = gw / (CK*CC);
    int r = gw % (CK*CC);
    int k = r / CC, c = r % CC;

    // A_logs shape (K*C, 1)
    float An = -__expf(__ldg(&Alogs[k*CC + c])) * 1.4426950408889634f; // * log2(e)
    float Dv = __ldg(&Ds[k*CC + c]);

    const float2* dd = g_dd + ((b*CK + k)*CC + c)*CL;
    const float2* bc = g_bc + (b*CK + k)*CL;
    const float*  up = g_u + (b*CC + c)*CL;
    float*        yo = (k == 0 ? g_y0 : g_y1) + (b*CC + c)*CL;

    const int CHK = CL / 32;   // 512
    int s0 = lane * CHK;

    float P = 1.f, S = 0.f;

    // pass 1: per-lane local affine aggregate (seq order; k=1 walks physical reversed)
    for (int tt = 0; tt < CHK; tt++){
        int s = s0 + tt;
        int p = k ? (CL-1 - s) : s;
        float2 d  = dd[p];
        float2 bv = bc[p];
        float a = ex2f(d.x * An);
        S = fmaf(a, S, d.y * bv.x);
        P *= a;
    }

    // warp inclusive scan of affine maps (earlier applied first)
    const unsigned FULL = 0xffffffffu;
    #pragma unroll
    for (int off = 1; off < 32; off <<= 1){
        float pp = __shfl_up_sync(FULL, P, off);
        float ss = __shfl_up_sync(FULL, S, off);
        if (lane >= off){
            S = fmaf(ss, P, S);
            P *= pp;
        }
    }
    float hs = __shfl_up_sync(FULL, S, 1);
    float h = lane ? hs : 0.f;

    // pass 2: recompute with correct entry state, emit y
    for (int tt = 0; tt < CHK; tt++){
        int s = s0 + tt;
        int p = k ? (CL-1 - s) : s;
        float2 d  = dd[p];
        float2 bv = bc[p];
        float a = ex2f(d.x * An);
        h = fmaf(a, h, d.y * bv.x);
        yo[p] = fmaf(h, bv.y, Dv * up[p]);
    }
}

// ---------------- K5+6: fused LayerNorm(channel) * silu(z), out_proj GEMM, scale ----------------
__global__ void k_out(const float* __restrict__ onw, const float* __restrict__ onb,
                      const float* __restrict__ sw, float* __restrict__ out){
    __shared__ float xsm[CC][68];
    __shared__ float red[4][64], red2[4][64];
    __shared__ float mu[64], rs[64];
    int b  = blockIdx.y;
    int l0 = blockIdx.x * 64;
    int t  = threadIdx.x;

    for (int i = t; i < CC*64; i += 256){
        int c = i >> 6, l = i & 63;
        int g = (b*CC + c)*CL + l0 + l;
        xsm[c][l] = g_y0[g] + g_y1[g];
    }
    __syncthreads();

    int col = t & 63, part = t >> 6;     // 4 partials per column
    float s = 0.f, s2 = 0.f;
    for (int c = part; c < CC; c += 4){
        float v = xsm[c][col];
        s += v; s2 = fmaf(v, v, s2);
    }
    red[part][col] = s; red2[part][col] = s2;
    __syncthreads();
    if (t < 64){
        float m  = (red[0][t]+red[1][t]+red[2][t]+red[3][t]) * (1.f/CC);
        float q  = (red2[0][t]+red2[1][t]+red2[2][t]+red2[3][t]) * (1.f/CC);
        mu[t] = m;
        rs[t] = rsqrtf(q - m*m + 1e-5f);
    }
    __syncthreads();

    for (int i = t; i < CC*64; i += 256){
        int c = i >> 6, l = i & 63;
        float v = (xsm[c][l] - mu[l]) * rs[l] * __ldg(&onw[c]) + __ldg(&onb[c]);
        v *= g_z[(b*CC + c)*CL + l0 + l];   // already silu(z)
        xsm[c][l] = v;
    }
    __syncthreads();

    // GEMM 96 x 64
    int to = t & 15, tl = t >> 4;
    int o0 = to * 6;
    int lb = tl * 4;
    float acc[6][4];
    #pragma unroll
    for (int j = 0; j < 6; j++)
        #pragma unroll
        for (int i = 0; i < 4; i++) acc[j][i] = 0.f;

    #pragma unroll 4
    for (int c = 0; c < CC; c++){
        float4 xv = *(const float4*)&xsm[c][lb];
        const float2* wp = (const float2*)&g_wt2[c*CC + o0];
        float2 w0 = wp[0], w1 = wp[1], w2 = wp[2];
        float wv[6] = {w0.x,w0.y, w1.x,w1.y, w2.x,w2.y};
        float xr[4] = {xv.x,xv.y,xv.z,xv.w};
        #pragma unroll
        for (int j = 0; j < 6; j++)
            #pragma unroll
            for (int i = 0; i < 4; i++)
                acc[j][i] = fmaf(wv[j], xr[i], acc[j][i]);
    }
    __syncthreads();

    #pragma unroll
    for (int j = 0; j < 6; j++)
        #pragma unroll
        for (int i = 0; i < 4; i++)
            xsm[o0 + j][lb + i] = acc[j][i];
    __syncthreads();

    for (int i = t; i < CC*64; i += 256){
        int o = i >> 6, l = i & 63;
        out[(b*CC + o)*CL + l0 + l] = xsm[o][l] * __ldg(&sw[o]);
    }
}

// ---------------- launch ----------------
extern "C" void kernel_launch(void* const* d_in, const int* in_sizes, int n_in,
                              void* d_out, int out_size){
    const float* x         = (const float*)d_in[0];
    const float* in_proj_w = (const float*)d_in[1];
    const float* conv_w    = (const float*)d_in[2];
    const float* conv_b    = (const float*)d_in[3];
    const float* x_proj_w  = (const float*)d_in[4];
    const float* dt_proj_w = (const float*)d_in[5];
    const float* dt_proj_b = (const float*)d_in[6];
    const float* A_logs    = (const float*)d_in[7];
    const float* Ds        = (const float*)d_in[8];
    const float* onw       = (const float*)d_in[9];
    const float* onb       = (const float*)d_in[10];
    const float* out_projw = (const float*)d_in[11];
    const float* scale_w   = (const float*)d_in[12];
    float* out = (float*)d_out;

    dim3 gt((CO*CC + 255)/256);
    k_transpose<<<gt, 256>>>(in_proj_w, out_projw);

    dim3 g1(CL/64, CB);
    k_inproj<<<g1, 256>>>(x);
    k_conv<<<(CB*CC*CL)/256, 256>>>(conv_w, conv_b);
    k_xproj<<<g1, 256>>>(x_proj_w, dt_proj_w, dt_proj_b);
    k_scan<<<192, 128>>>(A_logs, Ds);
    k_out<<<g1, 256>>>(onw, onb, scale_w, out);
}

// round 4
// speedup vs baseline: 2.4232x; 2.4232x over previous
#include <cuda_runtime.h>

#define CB 4
#define CC 96
#define CHh 128
#define CWw 128
#define CL (CHh*CWw)      // 16384
#define CK 2
#define CR 6
#define CD 8              // R + 2N = 8 rows of x_proj output
#define CO (2*CC)         // 192

typedef unsigned long long ull;

// ---------------- device scratch (allocation-free) ----------------
__device__ __align__(16) float  g_xc[CB*CC*CL];
__device__ __align__(16) float  g_z [CB*CC*CL];     // silu(z)
__device__ __align__(16) float  g_u [CB*CC*CL];     // post conv+silu
__device__ __align__(16) float2 g_dd[CB*CK*CC*CL];  // {delta, delta*u}
__device__ __align__(16) float2 g_bc[CB*CK*CL];     // {B, C}
__device__ __align__(16) float  g_y0[CB*CC*CL];
__device__ __align__(16) float  g_y1[CB*CC*CL];
__device__ __align__(16) float  g_wt1[CC*CO];       // in_proj^T  [c][o]
__device__ __align__(16) float  g_wt2[CC*CC];       // out_proj^T [c][o]
__device__ __align__(16) float  g_wtx[CC*16];       // x_proj^T   [c][kd]

__device__ __forceinline__ float ex2f(float x){
    float y; asm("ex2.approx.f32 %0, %1;" : "=f"(y) : "f"(x)); return y;
}
__device__ __forceinline__ float sigmoidf_(float x){
    return 1.f / (1.f + __expf(-x));
}
__device__ __forceinline__ ull packf2(float lo, float hi){
    ull r; asm("mov.b64 %0, {%1,%2};" : "=l"(r) : "f"(lo), "f"(hi)); return r;
}
__device__ __forceinline__ void unpackf2(ull v, float& lo, float& hi){
    asm("mov.b64 {%0,%1}, %2;" : "=f"(lo), "=f"(hi) : "l"(v));
}
__device__ __forceinline__ ull fmaf2(ull a, ull b, ull c){
    ull d; asm("fma.rn.f32x2 %0, %1, %2, %3;" : "=l"(d) : "l"(a), "l"(b), "l"(c)); return d;
}

// ---------------- K0: transpose weights ----------------
__global__ void k_transpose(const float* __restrict__ w1, const float* __restrict__ w2,
                            const float* __restrict__ xw){
    int t = blockIdx.x*256 + threadIdx.x;
    if (t < CO*CC){ int o = t / CC, c = t % CC; g_wt1[c*CO + o] = w1[t]; }
    if (t < CC*CC){ int o = t / CC, c = t % CC; g_wt2[c*CC + o] = w2[t]; }
    if (t < 16*CC){ int kd = t / CC, c = t % CC; g_wtx[c*16 + kd] = xw[t]; }
}

// ---------------- K1: in_proj GEMM 192x96 (f32x2 packed) ----------------
__global__ void k_inproj(const float* __restrict__ x){
    __shared__ float xsm[CC][68];
    int b  = blockIdx.y;
    int l0 = blockIdx.x * 64;
    int t  = threadIdx.x;

    for (int i = t; i < CC*64; i += 256){
        int c = i >> 6, l = i & 63;
        xsm[c][l] = x[(b*CC + c)*CL + l0 + l];
    }
    __syncthreads();

    int to = t & 15, tl = t >> 4;
    int o0 = to * 12;
    int lb = tl * 4;

    ull acc[6][4];
    #pragma unroll
    for (int jj = 0; jj < 6; jj++)
        #pragma unroll
        for (int i = 0; i < 4; i++) acc[jj][i] = 0ull;

    #pragma unroll 4
    for (int c = 0; c < CC; c++){
        float4 xv = *(const float4*)&xsm[c][lb];
        const float4* wp = (const float4*)&g_wt1[c*CO + o0];
        float4 w0 = wp[0], w1 = wp[1], w2 = wp[2];
        ull pw[6] = {packf2(w0.x,w0.y), packf2(w0.z,w0.w),
                     packf2(w1.x,w1.y), packf2(w1.z,w1.w),
                     packf2(w2.x,w2.y), packf2(w2.z,w2.w)};
        ull px[4] = {packf2(xv.x,xv.x), packf2(xv.y,xv.y),
                     packf2(xv.z,xv.z), packf2(xv.w,xv.w)};
        #pragma unroll
        for (int jj = 0; jj < 6; jj++)
            #pragma unroll
            for (int i = 0; i < 4; i++)
                acc[jj][i] = fmaf2(pw[jj], px[i], acc[jj][i]);
    }
    __syncthreads();

    for (int half = 0; half < 2; half++){
        if ((to < 8) == (half == 0)){
            int ob = o0 - half*96;
            #pragma unroll
            for (int jj = 0; jj < 6; jj++)
                #pragma unroll
                for (int i = 0; i < 4; i++){
                    float lo, hi; unpackf2(acc[jj][i], lo, hi);
                    xsm[ob + 2*jj    ][lb + i] = lo;
                    xsm[ob + 2*jj + 1][lb + i] = hi;
                }
        }
        __syncthreads();
        for (int i = t; i < CC*64; i += 256){
            int row = i >> 6, l = i & 63;
            float v = xsm[row][l];
            int idx = (b*CC + row)*CL + l0 + l;
            if (half == 0) g_xc[idx] = v;
            else           g_z[idx]  = v * sigmoidf_(v);
        }
        __syncthreads();
    }
}

// ---------------- K2: depthwise 3x3 conv + bias + SiLU ----------------
__global__ void k_conv(const float* __restrict__ cw, const float* __restrict__ cb){
    int idx = blockIdx.x*256 + threadIdx.x;
    if (idx >= CB*CC*CL) return;
    int w  = idx & (CWw-1);
    int h  = (idx >> 7) & (CHh-1);
    int bc = idx >> 14;
    int c  = bc % CC;
    const float* src = g_xc + bc*CL;
    float wl[9];
    #pragma unroll
    for (int j = 0; j < 9; j++) wl[j] = __ldg(&cw[c*9 + j]);
    float acc = __ldg(&cb[c]);
    #pragma unroll
    for (int dh = -1; dh <= 1; dh++){
        int hh = h + dh;
        if (hh < 0 || hh >= CHh) continue;
        #pragma unroll
        for (int dw = -1; dw <= 1; dw++){
            int ww = w + dw;
            if (ww < 0 || ww >= CWw) continue;
            acc = fmaf(wl[(dh+1)*3 + (dw+1)], src[hh*CWw + ww], acc);
        }
    }
    g_u[idx] = acc * sigmoidf_(acc);
}

// ---------------- K3: x_proj (register-resident restructure) ----------------
__global__ void k_xproj(const float* __restrict__ dtw, const float* __restrict__ dtb){
    __shared__ float usm[CC][65];
    __shared__ float dsm[16][65];
    int b  = blockIdx.y;
    int p0 = blockIdx.x * 64;
    int t  = threadIdx.x;

    for (int i = t; i < CC*64; i += 256){
        int c = i >> 6, pp = i & 63;
        usm[c][pp] = g_u[(b*CC + c)*CL + p0 + pp];
    }
    __syncthreads();

    // projection: thread = (row-group to: 4 rows, pp tl)
    {
        int to = t & 3, tl = t >> 2;           // tl in 0..63
        float acc0 = 0.f, acc1 = 0.f, acc2 = 0.f, acc3 = 0.f;
        #pragma unroll 4
        for (int c = 0; c < CC; c++){
            float xv = usm[c][tl];
            float4 wv = *(const float4*)&g_wtx[c*16 + to*4];
            acc0 = fmaf(wv.x, xv, acc0);
            acc1 = fmaf(wv.y, xv, acc1);
            acc2 = fmaf(wv.z, xv, acc2);
            acc3 = fmaf(wv.w, xv, acc3);
        }
        float accs[4] = {acc0, acc1, acc2, acc3};
        #pragma unroll
        for (int j = 0; j < 4; j++){
            int kd = to*4 + j;
            dsm[kd][tl] = accs[j];
            int k = kd >> 3, d = kd & 7;
            if (d >= CR){
                float* bcf = (float*)&g_bc[(b*CK + k)*CL + p0 + tl];
                bcf[d - CR] = accs[j];   // d==6 -> B (.x), d==7 -> C (.y)
            }
        }
    }
    __syncthreads();

    // delta: thread = (c-group cg: 24 channels, pp tl2), both k
    {
        int tl2 = t & 63, cg = t >> 6;         // cg in 0..3
        float dt0[CR], dt1[CR];
        #pragma unroll
        for (int r = 0; r < CR; r++){ dt0[r] = dsm[r][tl2]; dt1[r] = dsm[8+r][tl2]; }
        int c0 = cg * 24;
        #pragma unroll 2
        for (int k = 0; k < CK; k++){
            const float* dts = k ? dt1 : dt0;
            for (int cc = 0; cc < 24; cc++){
                int c = c0 + cc;
                const float* dwr = dtw + (k*CC + c)*CR;
                float s = __ldg(&dtb[k*CC + c]);
                #pragma unroll
                for (int r = 0; r < CR; r++) s = fmaf(__ldg(&dwr[r]), dts[r], s);
                float delta = (s > 20.f) ? s : log1pf(__expf(s));
                float uv = usm[c][tl2];
                g_dd[((b*CK + k)*CC + c)*CL + p0 + tl2] = make_float2(delta, delta*uv);
            }
        }
    }
}

// ---------------- K4: single-pass tile-sequential block scan ----------------
// block = one (b,k,c) sequence; 256 threads; 8 tiles of 2048; 8 items/thread.
#define TILE 2048
#define ITEMS 8
__global__ __launch_bounds__(256) void k_scan(const float* __restrict__ Alogs){
    int blk = blockIdx.x;                 // c fastest for bc L2 reuse
    int c = blk % CC;
    int k = (blk / CC) & 1;
    int b = blk / (CC*CK);
    int t = threadIdx.x;
    int w = t >> 5, lane = t & 31;

    float An = -__expf(__ldg(&Alogs[k*CC + c])) * 1.4426950408889634f;

    const float2* dd = g_dd + ((b*CK + k)*CC + c)*CL;
    const float2* bc = g_bc + (b*CK + k)*CL;
    float*        yo = (k ? g_y1 : g_y0) + (b*CC + c)*CL;

    __shared__ float2 sdd[TILE + TILE/ITEMS];   // padded: e -> e + e/8
    __shared__ float2 sbc[TILE + TILE/ITEMS];
    __shared__ float  sP[8], sS[8], sPe[8], sSe[8];
    __shared__ float  sCarry;
    if (t == 0) sCarry = 0.f;

    const unsigned FULL = 0xffffffffu;

    for (int tile = 0; tile < CL/TILE; tile++){
        int T0 = tile * TILE;   // sequence-space base

        // ---- coalesced load into smem (sequence order) ----
        if (k == 0){
            const float4* src = (const float4*)(dd + T0);
            const float4* srb = (const float4*)(bc + T0);
            #pragma unroll
            for (int ii = 0; ii < TILE/2/256; ii++){
                int i = ii*256 + t;
                int e = i*2, m = e + (e >> 3);
                float4 v = src[i];
                sdd[m]   = make_float2(v.x, v.y);
                sdd[m+1] = make_float2(v.z, v.w);
                float4 u2 = srb[i];
                sbc[m]   = make_float2(u2.x, u2.y);
                sbc[m+1] = make_float2(u2.z, u2.w);
            }
        } else {
            int P0 = CL - T0 - TILE;
            const float4* src = (const float4*)(dd + P0);
            const float4* srb = (const float4*)(bc + P0);
            #pragma unroll
            for (int ii = 0; ii < TILE/2/256; ii++){
                int i = ii*256 + t;
                int e1 = TILE-1 - 2*i;          // seq offset of phys P0+2i
                int e2 = e1 - 1;                // phys P0+2i+1
                float4 v = src[i];
                sdd[e1 + (e1>>3)] = make_float2(v.x, v.y);
                sdd[e2 + (e2>>3)] = make_float2(v.z, v.w);
                float4 u2 = srb[i];
                sbc[e1 + (e1>>3)] = make_float2(u2.x, u2.y);
                sbc[e2 + (e2>>3)] = make_float2(u2.z, u2.w);
            }
        }
        __syncthreads();
        float h_in = sCarry;

        // ---- thread-local items into registers + local affine aggregate ----
        float2 ldd[ITEMS], lbc[ITEMS];
        #pragma unroll
        for (int i2 = 0; i2 < ITEMS; i2++){
            ldd[i2] = sdd[t*9 + i2];
            lbc[i2] = sbc[t*9 + i2];
        }
        float P = 1.f, S = 0.f;
        #pragma unroll
        for (int i2 = 0; i2 < ITEMS; i2++){
            float a = ex2f(ldd[i2].x * An);
            S = fmaf(a, S, ldd[i2].y * lbc[i2].x);
            P *= a;
        }

        // ---- warp inclusive scan of (P,S) ----
        float Pi = P, Si = S;
        #pragma unroll
        for (int off = 1; off < 32; off <<= 1){
            float pp = __shfl_up_sync(FULL, Pi, off);
            float ss = __shfl_up_sync(FULL, Si, off);
            if (lane >= off){ Si = fmaf(ss, Pi, Si); Pi *= pp; }
        }
        float Pex = __shfl_up_sync(FULL, Pi, 1);
        float Sex = __shfl_up_sync(FULL, Si, 1);
        if (lane == 0){ Pex = 1.f; Sex = 0.f; }
        if (lane == 31){ sP[w] = Pi; sS[w] = Si; }
        __syncthreads();

        // ---- cross-warp serial combine + tile carry ----
        if (t == 0){
            float cp = 1.f, cs = 0.f;
            #pragma unroll
            for (int ww = 0; ww < 8; ww++){
                sPe[ww] = cp; sSe[ww] = cs;
                float Pw = sP[ww], Sw = sS[ww];
                cs = fmaf(Pw, cs, Sw);
                cp = Pw * cp;
            }
            sCarry = fmaf(cp, h_in, cs);
        }
        __syncthreads();

        // ---- entry state and second pass over registers ----
        float hw = fmaf(sPe[w], h_in, sSe[w]);
        float h  = fmaf(Pex, hw, Sex);
        float yv[ITEMS];
        #pragma unroll
        for (int i2 = 0; i2 < ITEMS; i2++){
            float a = ex2f(ldd[i2].x * An);
            h = fmaf(a, h, ldd[i2].y * lbc[i2].x);
            yv[i2] = h * lbc[i2].y;
        }

        // ---- coalesced store ----
        int base = t * ITEMS;
        if (k == 0){
            float4* dst = (float4*)(yo + T0 + base);
            dst[0] = make_float4(yv[0], yv[1], yv[2], yv[3]);
            dst[1] = make_float4(yv[4], yv[5], yv[6], yv[7]);
        } else {
            float4* dst = (float4*)(yo + (CL - T0 - base - 8));
            dst[0] = make_float4(yv[7], yv[6], yv[5], yv[4]);
            dst[1] = make_float4(yv[3], yv[2], yv[1], yv[0]);
        }
        __syncthreads();
    }
}

// ---------------- K5: LN * silu(z) gate, out_proj GEMM (f32x2), scale ----------------
__global__ void k_out(const float* __restrict__ onw, const float* __restrict__ onb,
                      const float* __restrict__ Ds,
                      const float* __restrict__ sw, float* __restrict__ out){
    __shared__ float xsm[CC][68];
    __shared__ float red[4][64], red2[4][64];
    __shared__ float mu[64], rs[64];
    int b  = blockIdx.y;
    int l0 = blockIdx.x * 64;
    int t  = threadIdx.x;

    for (int i = t; i < CC*64; i += 256){
        int c = i >> 6, l = i & 63;
        int g = (b*CC + c)*CL + l0 + l;
        float dsum = __ldg(&Ds[c]) + __ldg(&Ds[CC + c]);
        xsm[c][l] = g_y0[g] + g_y1[g] + dsum * g_u[g];
    }
    __syncthreads();

    int col = t & 63, part = t >> 6;
    float s = 0.f, s2 = 0.f;
    for (int c = part; c < CC; c += 4){
        float v = xsm[c][col];
        s += v; s2 = fmaf(v, v, s2);
    }
    red[part][col] = s; red2[part][col] = s2;
    __syncthreads();
    if (t < 64){
        float m  = (red[0][t]+red[1][t]+red[2][t]+red[3][t]) * (1.f/CC);
        float q  = (red2[0][t]+red2[1][t]+red2[2][t]+red2[3][t]) * (1.f/CC);
        mu[t] = m;
        rs[t] = rsqrtf(q - m*m + 1e-5f);
    }
    __syncthreads();

    for (int i = t; i < CC*64; i += 256){
        int c = i >> 6, l = i & 63;
        float v = (xsm[c][l] - mu[l]) * rs[l] * __ldg(&onw[c]) + __ldg(&onb[c]);
        v *= g_z[(b*CC + c)*CL + l0 + l];
        xsm[c][l] = v;
    }
    __syncthreads();

    int to = t & 15, tl = t >> 4;
    int o0 = to * 6;
    int lb = tl * 4;
    ull acc[3][4];
    #pragma unroll
    for (int jj = 0; jj < 3; jj++)
        #pragma unroll
        for (int i = 0; i < 4; i++) acc[jj][i] = 0ull;

    #pragma unroll 4
    for (int c = 0; c < CC; c++){
        float4 xv = *(const float4*)&xsm[c][lb];
        const ull* wp = (const ull*)&g_wt2[c*CC + o0];
        ull pw0 = wp[0], pw1 = wp[1], pw2 = wp[2];
        ull px[4] = {packf2(xv.x,xv.x), packf2(xv.y,xv.y),
                     packf2(xv.z,xv.z), packf2(xv.w,xv.w)};
        #pragma unroll
        for (int i = 0; i < 4; i++){
            acc[0][i] = fmaf2(pw0, px[i], acc[0][i]);
            acc[1][i] = fmaf2(pw1, px[i], acc[1][i]);
            acc[2][i] = fmaf2(pw2, px[i], acc[2][i]);
        }
    }
    __syncthreads();

    #pragma unroll
    for (int jj = 0; jj < 3; jj++)
        #pragma unroll
        for (int i = 0; i < 4; i++){
            float lo, hi; unpackf2(acc[jj][i], lo, hi);
            xsm[o0 + 2*jj    ][lb + i] = lo;
            xsm[o0 + 2*jj + 1][lb + i] = hi;
        }
    __syncthreads();

    for (int i = t; i < CC*64; i += 256){
        int o = i >> 6, l = i & 63;
        out[(b*CC + o)*CL + l0 + l] = xsm[o][l] * __ldg(&sw[o]);
    }
}

// ---------------- launch ----------------
extern "C" void kernel_launch(void* const* d_in, const int* in_sizes, int n_in,
                              void* d_out, int out_size){
    const float* x         = (const float*)d_in[0];
    const float* in_proj_w = (const float*)d_in[1];
    const float* conv_w    = (const float*)d_in[2];
    const float* conv_b    = (const float*)d_in[3];
    const float* x_proj_w  = (const float*)d_in[4];
    const float* dt_proj_w = (const float*)d_in[5];
    const float* dt_proj_b = (const float*)d_in[6];
    const float* A_logs    = (const float*)d_in[7];
    const float* Ds        = (const float*)d_in[8];
    const float* onw       = (const float*)d_in[9];
    const float* onb       = (const float*)d_in[10];
    const float* out_projw = (const float*)d_in[11];
    const float* scale_w   = (const float*)d_in[12];
    float* out = (float*)d_out;

    k_transpose<<<(CO*CC + 255)/256, 256>>>(in_proj_w, out_projw, x_proj_w);

    dim3 g1(CL/64, CB);
    k_inproj<<<g1, 256>>>(x);
    k_conv<<<(CB*CC*CL)/256, 256>>>(conv_w, conv_b);
    k_xproj<<<g1, 256>>>(dt_proj_w, dt_proj_b);
    k_scan<<<CB*CK*CC, 256>>>(A_logs);
    k_out<<<g1, 256>>>(onw, onb, Ds, scale_w, out);
}

// round 5
// speedup vs baseline: 2.6039x; 1.0746x over previous
#include <cuda_runtime.h>

#define CB 4
#define CC 96
#define CHh 128
#define CWw 128
#define CL (CHh*CWw)      // 16384
#define CK 2
#define CR 6
#define CO (2*CC)         // 192

typedef unsigned long long ull;

// ---------------- device scratch (allocation-free) ----------------
__device__ __align__(16) float  g_xc[CB*CC*CL];
__device__ __align__(16) float  g_z [CB*CC*CL];     // silu(z)
__device__ __align__(16) float  g_u [CB*CC*CL];     // post conv+silu
__device__ __align__(16) float  g_db8[CB*CK*CL*8];  // {dts[6], B, C} per (b,k,p)
__device__ __align__(16) float  g_y0[CB*CC*CL];
__device__ __align__(16) float  g_y1[CB*CC*CL];
__device__ __align__(16) float  g_wt1[CC*CO];       // in_proj^T  [c][o]
__device__ __align__(16) float  g_wt2[CC*CC];       // out_proj^T [c][o]
__device__ __align__(16) float  g_wtx[CC*16];       // x_proj^T   [c][kd]

__device__ __forceinline__ float ex2f(float x){
    float y; asm("ex2.approx.f32 %0, %1;" : "=f"(y) : "f"(x)); return y;
}
__device__ __forceinline__ float lg2f(float x){
    float y; asm("lg2.approx.f32 %0, %1;" : "=f"(y) : "f"(x)); return y;
}
__device__ __forceinline__ float sigmoidf_(float x){
    return 1.f / (1.f + __expf(-x));
}
__device__ __forceinline__ ull packf2(float lo, float hi){
    ull r; asm("mov.b64 %0, {%1,%2};" : "=l"(r) : "f"(lo), "f"(hi)); return r;
}
__device__ __forceinline__ void unpackf2(ull v, float& lo, float& hi){
    asm("mov.b64 {%0,%1}, %2;" : "=f"(lo), "=f"(hi) : "l"(v));
}
__device__ __forceinline__ ull fmaf2(ull a, ull b, ull c){
    ull d; asm("fma.rn.f32x2 %0, %1, %2, %3;" : "=l"(d) : "l"(a), "l"(b), "l"(c)); return d;
}

// ---------------- K0: transpose weights ----------------
__global__ void k_transpose(const float* __restrict__ w1, const float* __restrict__ w2,
                            const float* __restrict__ xw){
    int t = blockIdx.x*256 + threadIdx.x;
    if (t < CO*CC){ int o = t / CC, c = t % CC; g_wt1[c*CO + o] = w1[t]; }
    if (t < CC*CC){ int o = t / CC, c = t % CC; g_wt2[c*CC + o] = w2[t]; }
    if (t < 16*CC){ int kd = t / CC, c = t % CC; g_wtx[c*16 + kd] = xw[t]; }
}

// ---------------- K1: in_proj GEMM 192x96 (f32x2 packed) ----------------
__global__ void k_inproj(const float* __restrict__ x){
    __shared__ float xsm[CC][68];
    int b  = blockIdx.y;
    int l0 = blockIdx.x * 64;
    int t  = threadIdx.x;

    for (int i = t; i < CC*64; i += 256){
        int c = i >> 6, l = i & 63;
        xsm[c][l] = x[(b*CC + c)*CL + l0 + l];
    }
    __syncthreads();

    int to = t & 15, tl = t >> 4;
    int o0 = to * 12;
    int lb = tl * 4;

    ull acc[6][4];
    #pragma unroll
    for (int jj = 0; jj < 6; jj++)
        #pragma unroll
        for (int i = 0; i < 4; i++) acc[jj][i] = 0ull;

    #pragma unroll 4
    for (int c = 0; c < CC; c++){
        float4 xv = *(const float4*)&xsm[c][lb];
        const float4* wp = (const float4*)&g_wt1[c*CO + o0];
        float4 w0 = wp[0], w1 = wp[1], w2 = wp[2];
        ull pw[6] = {packf2(w0.x,w0.y), packf2(w0.z,w0.w),
                     packf2(w1.x,w1.y), packf2(w1.z,w1.w),
                     packf2(w2.x,w2.y), packf2(w2.z,w2.w)};
        ull px[4] = {packf2(xv.x,xv.x), packf2(xv.y,xv.y),
                     packf2(xv.z,xv.z), packf2(xv.w,xv.w)};
        #pragma unroll
        for (int jj = 0; jj < 6; jj++)
            #pragma unroll
            for (int i = 0; i < 4; i++)
                acc[jj][i] = fmaf2(pw[jj], px[i], acc[jj][i]);
    }
    __syncthreads();

    for (int half = 0; half < 2; half++){
        if ((to < 8) == (half == 0)){
            int ob = o0 - half*96;
            #pragma unroll
            for (int jj = 0; jj < 6; jj++)
                #pragma unroll
                for (int i = 0; i < 4; i++){
                    float lo, hi; unpackf2(acc[jj][i], lo, hi);
                    xsm[ob + 2*jj    ][lb + i] = lo;
                    xsm[ob + 2*jj + 1][lb + i] = hi;
                }
        }
        __syncthreads();
        for (int i = t; i < CC*64; i += 256){
            int row = i >> 6, l = i & 63;
            float v = xsm[row][l];
            int idx = (b*CC + row)*CL + l0 + l;
            if (half == 0) g_xc[idx] = v;
            else           g_z[idx]  = v * sigmoidf_(v);
        }
        __syncthreads();
    }
}

// ---------------- K2: depthwise 3x3 conv + bias + SiLU ----------------
__global__ void k_conv(const float* __restrict__ cw, const float* __restrict__ cb){
    int idx = blockIdx.x*256 + threadIdx.x;
    if (idx >= CB*CC*CL) return;
    int w  = idx & (CWw-1);
    int h  = (idx >> 7) & (CHh-1);
    int bc = idx >> 14;
    int c  = bc % CC;
    const float* src = g_xc + bc*CL;
    float wl[9];
    #pragma unroll
    for (int j = 0; j < 9; j++) wl[j] = __ldg(&cw[c*9 + j]);
    float acc = __ldg(&cb[c]);
    #pragma unroll
    for (int dh = -1; dh <= 1; dh++){
        int hh = h + dh;
        if (hh < 0 || hh >= CHh) continue;
        #pragma unroll
        for (int dw = -1; dw <= 1; dw++){
            int ww = w + dw;
            if (ww < 0 || ww >= CWw) continue;
            acc = fmaf(wl[(dh+1)*3 + (dw+1)], src[hh*CWw + ww], acc);
        }
    }
    g_u[idx] = acc * sigmoidf_(acc);
}

// ---------------- K3: x_proj only (C->16 rows), write db8 ----------------
__global__ void k_proj(){
    __shared__ float usm[CC][65];
    int b  = blockIdx.y;
    int p0 = blockIdx.x * 64;
    int t  = threadIdx.x;

    for (int i = t; i < CC*64; i += 256){
        int c = i >> 6, pp = i & 63;
        usm[c][pp] = g_u[(b*CC + c)*CL + p0 + pp];
    }
    __syncthreads();

    int to = t & 3, tl = t >> 2;           // 4 rows x 64 positions
    float acc0 = 0.f, acc1 = 0.f, acc2 = 0.f, acc3 = 0.f;
    #pragma unroll 4
    for (int c = 0; c < CC; c++){
        float xv = usm[c][tl];
        float4 wv = *(const float4*)&g_wtx[c*16 + to*4];
        acc0 = fmaf(wv.x, xv, acc0);
        acc1 = fmaf(wv.y, xv, acc1);
        acc2 = fmaf(wv.z, xv, acc2);
        acc3 = fmaf(wv.w, xv, acc3);
    }
    int k = to >> 1;
    *(float4*)&g_db8[(((b*CK + k)*CL) + p0 + tl)*8 + (to & 1)*4] =
        make_float4(acc0, acc1, acc2, acc3);
}

// ---------------- K4: scan with on-the-fly delta ----------------
// block = one (b,k,c); 256 threads; 8 tiles of 2048; 8 items/thread.
#define TILE 2048
#define ITEMS 8
#define LOG2E 1.4426950408889634f
#define LN2   0.6931471805599453f
__global__ __launch_bounds__(256) void k_scan(const float* __restrict__ Alogs,
                                              const float* __restrict__ dtw,
                                              const float* __restrict__ dtb,
                                              const float* __restrict__ Dsp){
    int blk = blockIdx.x;
    int c = blk % CC;
    int k = (blk / CC) & 1;
    int b = blk / (CC*CK);
    int t = threadIdx.x;
    int w = t >> 5, lane = t & 31;

    float An = -__expf(__ldg(&Alogs[k*CC + c]));            // natural, negative
    float Dv = __ldg(&Dsp[k*CC + c]);
    float dw[CR];
    #pragma unroll
    for (int r = 0; r < CR; r++) dw[r] = __ldg(&dtw[(k*CC + c)*CR + r]);
    float db = __ldg(&dtb[k*CC + c]);

    const float4* dbp = (const float4*)(g_db8 + (ull)(b*CK + k)*CL*8);
    const float*  up  = g_u + (b*CC + c)*CL;
    float*        yo  = (k ? g_y1 : g_y0) + (b*CC + c)*CL;

    __shared__ float4 sv[TILE + TILE/ITEMS];   // {a, x, C, D*u}, padded e -> e+(e>>3)
    __shared__ float  sP[8], sS[8], sPe[8], sSe[8];
    __shared__ float  sCarry;
    if (t == 0) sCarry = 0.f;

    const unsigned FULL = 0xffffffffu;

    for (int tile = 0; tile < CL/TILE; tile++){
        int T0 = tile * TILE;                  // sequence base
        int P0 = k ? (CL - T0 - TILE) : T0;    // physical base

        // ---- load + compute {a, x, C, Du} into smem (sequence order) ----
        #pragma unroll
        for (int ii = 0; ii < TILE/256; ii++){
            int i = ii*256 + t;                // physical-local index
            int e = k ? (TILE-1 - i) : i;      // sequence-local index
            int p = P0 + i;
            float4 d0 = dbp[p*2];
            float4 d1 = dbp[p*2 + 1];
            float uv  = up[p];
            float s = db;
            s = fmaf(dw[0], d0.x, s); s = fmaf(dw[1], d0.y, s);
            s = fmaf(dw[2], d0.z, s); s = fmaf(dw[3], d0.w, s);
            s = fmaf(dw[4], d1.x, s); s = fmaf(dw[5], d1.y, s);
            float lg2v = (s > 20.f) ? s*LOG2E : lg2f(1.f + ex2f(s*LOG2E));
            float a = ex2f(An * lg2v);
            float delta = LN2 * lg2v;
            float xx = delta * uv * d1.z;      // delta*u*B
            sv[e + (e>>3)] = make_float4(a, xx, d1.w, Dv * uv);
        }
        __syncthreads();
        float h_in = sCarry;

        // ---- local affine aggregate from smem ----
        int base = t * 9;   // t*ITEMS + (t*ITEMS>>3)
        float P = 1.f, S = 0.f;
        #pragma unroll
        for (int i2 = 0; i2 < ITEMS; i2++){
            float4 v = sv[base + i2];
            S = fmaf(v.x, S, v.y);
            P *= v.x;
        }

        // ---- warp inclusive scan of (P,S) ----
        float Pi = P, Si = S;
        #pragma unroll
        for (int off = 1; off < 32; off <<= 1){
            float pp = __shfl_up_sync(FULL, Pi, off);
            float ss = __shfl_up_sync(FULL, Si, off);
            if (lane >= off){ Si = fmaf(ss, Pi, Si); Pi *= pp; }
        }
        float Pex = __shfl_up_sync(FULL, Pi, 1);
        float Sex = __shfl_up_sync(FULL, Si, 1);
        if (lane == 0){ Pex = 1.f; Sex = 0.f; }
        if (lane == 31){ sP[w] = Pi; sS[w] = Si; }
        __syncthreads();

        // ---- cross-warp serial combine + tile carry ----
        if (t == 0){
            float cp = 1.f, cs = 0.f;
            #pragma unroll
            for (int ww = 0; ww < 8; ww++){
                sPe[ww] = cp; sSe[ww] = cs;
                float Pw = sP[ww], Sw = sS[ww];
                cs = fmaf(Pw, cs, Sw);
                cp = Pw * cp;
            }
            sCarry = fmaf(cp, h_in, cs);
        }
        __syncthreads();

        // ---- final pass: emit y ----
        float hw = fmaf(sPe[w], h_in, sSe[w]);
        float h  = fmaf(Pex, hw, Sex);
        float yv[ITEMS];
        #pragma unroll
        for (int i2 = 0; i2 < ITEMS; i2++){
            float4 v = sv[base + i2];
            h = fmaf(v.x, h, v.y);
            yv[i2] = fmaf(h, v.z, v.w);        // h*C + D*u
        }

        // ---- coalesced store ----
        int sb = t * ITEMS;
        if (k == 0){
            float4* dst = (float4*)(yo + T0 + sb);
            dst[0] = make_float4(yv[0], yv[1], yv[2], yv[3]);
            dst[1] = make_float4(yv[4], yv[5], yv[6], yv[7]);
        } else {
            float4* dst = (float4*)(yo + (CL - T0 - sb - 8));
            dst[0] = make_float4(yv[7], yv[6], yv[5], yv[4]);
            dst[1] = make_float4(yv[3], yv[2], yv[1], yv[0]);
        }
        __syncthreads();
    }
}

// ---------------- K5: LN * silu(z) gate, out_proj GEMM (f32x2), scale ----------------
__global__ void k_out(const float* __restrict__ onw, const float* __restrict__ onb,
                      const float* __restrict__ sw, float* __restrict__ out){
    __shared__ float xsm[CC][68];
    __shared__ float red[4][64], red2[4][64];
    __shared__ float mu[64], rs[64];
    int b  = blockIdx.y;
    int l0 = blockIdx.x * 64;
    int t  = threadIdx.x;

    for (int i = t; i < CC*64; i += 256){
        int c = i >> 6, l = i & 63;
        int g = (b*CC + c)*CL + l0 + l;
        xsm[c][l] = g_y0[g] + g_y1[g];
    }
    __syncthreads();

    int col = t & 63, part = t >> 6;
    float s = 0.f, s2 = 0.f;
    for (int c = part; c < CC; c += 4){
        float v = xsm[c][col];
        s += v; s2 = fmaf(v, v, s2);
    }
    red[part][col] = s; red2[part][col] = s2;
    __syncthreads();
    if (t < 64){
        float m  = (red[0][t]+red[1][t]+red[2][t]+red[3][t]) * (1.f/CC);
        float q  = (red2[0][t]+red2[1][t]+red2[2][t]+red2[3][t]) * (1.f/CC);
        mu[t] = m;
        rs[t] = rsqrtf(q - m*m + 1e-5f);
    }
    __syncthreads();

    for (int i = t; i < CC*64; i += 256){
        int c = i >> 6, l = i & 63;
        float v = (xsm[c][l] - mu[l]) * rs[l] * __ldg(&onw[c]) + __ldg(&onb[c]);
        v *= g_z[(b*CC + c)*CL + l0 + l];
        xsm[c][l] = v;
    }
    __syncthreads();

    int to = t & 15, tl = t >> 4;
    int o0 = to * 6;
    int lb = tl * 4;
    ull acc[3][4];
    #pragma unroll
    for (int jj = 0; jj < 3; jj++)
        #pragma unroll
        for (int i = 0; i < 4; i++) acc[jj][i] = 0ull;

    #pragma unroll 4
    for (int c = 0; c < CC; c++){
        float4 xv = *(const float4*)&xsm[c][lb];
        const ull* wp = (const ull*)&g_wt2[c*CC + o0];
        ull pw0 = wp[0], pw1 = wp[1], pw2 = wp[2];
        ull px[4] = {packf2(xv.x,xv.x), packf2(xv.y,xv.y),
                     packf2(xv.z,xv.z), packf2(xv.w,xv.w)};
        #pragma unroll
        for (int i = 0; i < 4; i++){
            acc[0][i] = fmaf2(pw0, px[i], acc[0][i]);
            acc[1][i] = fmaf2(pw1, px[i], acc[1][i]);
            acc[2][i] = fmaf2(pw2, px[i], acc[2][i]);
        }
    }
    __syncthreads();

    #pragma unroll
    for (int jj = 0; jj < 3; jj++)
        #pragma unroll
        for (int i = 0; i < 4; i++){
            float lo, hi; unpackf2(acc[jj][i], lo, hi);
            xsm[o0 + 2*jj    ][lb + i] = lo;
            xsm[o0 + 2*jj + 1][lb + i] = hi;
        }
    __syncthreads();

    for (int i = t; i < CC*64; i += 256){
        int o = i >> 6, l = i & 63;
        out[(b*CC + o)*CL + l0 + l] = xsm[o][l] * __ldg(&sw[o]);
    }
}

// ---------------- launch ----------------
extern "C" void kernel_launch(void* const* d_in, const int* in_sizes, int n_in,
                              void* d_out, int out_size){
    const float* x         = (const float*)d_in[0];
    const float* in_proj_w = (const float*)d_in[1];
    const float* conv_w    = (const float*)d_in[2];
    const float* conv_b    = (const float*)d_in[3];
    const float* x_proj_w  = (const float*)d_in[4];
    const float* dt_proj_w = (const float*)d_in[5];
    const float* dt_proj_b = (const float*)d_in[6];
    const float* A_logs    = (const float*)d_in[7];
    const float* Ds        = (const float*)d_in[8];
    const float* onw       = (const float*)d_in[9];
    const float* onb       = (const float*)d_in[10];
    const float* out_projw = (const float*)d_in[11];
    const float* scale_w   = (const float*)d_in[12];
    float* out = (float*)d_out;

    k_transpose<<<(CO*CC + 255)/256, 256>>>(in_proj_w, out_projw, x_proj_w);

    dim3 g1(CL/64, CB);
    k_inproj<<<g1, 256>>>(x);
    k_conv<<<(CB*CC*CL)/256, 256>>>(conv_w, conv_b);
    k_proj<<<g1, 256>>>();
    k_scan<<<CB*CK*CC, 256>>>(A_logs, dt_proj_w, dt_proj_b, Ds);
    k_out<<<g1, 256>>>(onw, onb, scale_w, out);
}